// round 2
// baseline (speedup 1.0000x reference)
#include <cuda_runtime.h>
#include <cuda_bf16.h>

// Shapes (fixed): B=2, N=2048, K=48, A=4
// X: (B,N,4,3) f32; edge_idx: (B,N,48) i32; C: (B,N) i32
// out: (B,N,48,192) f32   [192 = 8a * 8b * 3comp, idx = a*24 + b*3 + c]
//
// Strategy:
//  - 1 CTA per (b,n), 384 threads.
//  - Stage self coords, 48 gathered neighbor coord rows, frame R, masks in smem.
//  - U_rot[b][a] = -U_rot[a][b], diag = 0  -> compute only 28 unique pairs per k.
//  - Results staged in padded smem tile (a-pitch 28 floats: conflict-free),
//    then copied out fully coalesced (thread t writes float4 f = t + 384*q).

#define BB 2
#define NN 2048
#define KK 48
#define EPS 0.1f
#define THREADS 384

#define APITCH 28            // floats per a-row in staging (24 data + 4 pad)
#define KPITCH (8 * APITCH)  // 224 floats per k tile

// 28 unique (a<b) pairs among 8 atoms
__constant__ unsigned char cPA[28] = {
    0,0,0,0,0,0,0,
    1,1,1,1,1,1,
    2,2,2,2,2,
    3,3,3,3,
    4,4,4,
    5,5,
    6};
__constant__ unsigned char cPB[28] = {
    1,2,3,4,5,6,7,
    2,3,4,5,6,7,
    3,4,5,6,7,
    4,5,6,7,
    5,6,7,
    6,7,
    7};

__global__ __launch_bounds__(THREADS) void edge_orient_kernel(
    const float* __restrict__ X,
    const int*   __restrict__ E,
    const int*   __restrict__ C,
    float*       __restrict__ out)
{
    const int bn = blockIdx.x;
    const int b  = bn >> 11;           // /NN
    const int t  = threadIdx.x;

    __shared__ __align__(16) float sXj[KK][12];
    __shared__ __align__(16) float sXi[12];
    __shared__ float sR[9];
    __shared__ float sMaskJ[KK];
    __shared__ float sMaskI;
    __shared__ __align__(16) float sOut[KK * KPITCH];   // 43008 B

    const int* e_row = E + (size_t)bn * KK;

    // ---- staging ----
    if (t < 12) sXi[t] = X[(size_t)bn * 12 + t];
    if (t < KK * 3) {                       // 144 threads, one float4 each
        const int nb = t / 3;
        const int q  = t % 3;
        const int j  = e_row[nb];
        const float4* src = (const float4*)(X + ((size_t)(b * NN + j)) * 12);
        ((float4*)&sXj[nb][0])[q] = src[q];
    }
    if (t >= 144 && t < 144 + KK) {
        const int nb = t - 144;
        const int j  = e_row[nb];
        sMaskJ[nb] = (C[b * NN + j] > 0) ? 1.0f : 0.0f;
    }
    if (t == 192) sMaskI = (C[bn] > 0) ? 1.0f : 0.0f;
    if (t == 193) {
        const float* xr = X + (size_t)bn * 12;
        float Nx = xr[0], Ny = xr[1], Nz = xr[2];
        float Ax = xr[3], Ay = xr[4], Az = xr[5];
        float Cx = xr[6], Cy = xr[7], Cz = xr[8];

        float ux = Nx - Ax, uy = Ny - Ay, uz = Nz - Az;
        float inv = rsqrtf(ux*ux + uy*uy + uz*uz + EPS);
        float n1x = ux*inv, n1y = uy*inv, n1z = uz*inv;

        float vx = Cx - Ax, vy = Cy - Ay, vz = Cz - Az;
        inv = rsqrtf(vx*vx + vy*vy + vz*vz + EPS);
        vx *= inv; vy *= inv; vz *= inv;

        float c2x = n1y*vz - n1z*vy;
        float c2y = n1z*vx - n1x*vz;
        float c2z = n1x*vy - n1y*vx;
        inv = rsqrtf(c2x*c2x + c2y*c2y + c2z*c2z + EPS);
        float n2x = c2x*inv, n2y = c2y*inv, n2z = c2z*inv;

        float c3x = n1y*n2z - n1z*n2y;
        float c3y = n1z*n2x - n1x*n2z;
        float c3z = n1x*n2y - n1y*n2x;
        inv = rsqrtf(c3x*c3x + c3y*c3y + c3z*c3z + EPS);

        sR[0] = n1x;     sR[1] = n1y;     sR[2] = n1z;
        sR[3] = n2x;     sR[4] = n2y;     sR[5] = n2z;
        sR[6] = c3x*inv; sR[7] = c3y*inv; sR[8] = c3z*inv;
    }
    __syncthreads();

    // ---- compute phase: thread = (k, p); p owns schedule slots 4p..4p+3 ----
    {
        const int k = t >> 3;
        const int p = t & 7;
        const float m = sMaskI * sMaskJ[k];
        float* outk = &sOut[k * KPITCH];

        const float n1x = sR[0], n1y = sR[1], n1z = sR[2];
        const float n2x = sR[3], n2y = sR[4], n2z = sR[5];
        const float n3x = sR[6], n3y = sR[7], n3z = sR[8];

#pragma unroll
        for (int i = 0; i < 4; i++) {
            const int s = p * 4 + i;
            if (s < 28) {
                const int a  = cPA[s];
                const int bb = cPB[s];
                const float* pa_ = (a  < 4) ? &sXi[a * 3]  : &sXj[k][(a  - 4) * 3];
                const float* pb_ = (bb < 4) ? &sXi[bb * 3] : &sXj[k][(bb - 4) * 3];
                const float dx = pb_[0] - pa_[0];
                const float dy = pb_[1] - pa_[1];
                const float dz = pb_[2] - pa_[2];
                const float inv = rsqrtf(dx*dx + dy*dy + dz*dz + EPS) * m;
                const float ux = dx * inv, uy = dy * inv, uz = dz * inv;
                const float r0 = ux*n1x + uy*n1y + uz*n1z;
                const float r1 = ux*n2x + uy*n2y + uz*n2z;
                const float r2 = ux*n3x + uy*n3y + uz*n3z;
                float* q1 = outk + a  * APITCH + bb * 3;   // U[a][b]
                q1[0] =  r0; q1[1] =  r1; q1[2] =  r2;
                float* q2 = outk + bb * APITCH + a  * 3;   // U[b][a] = -U[a][b]
                q2[0] = -r0; q2[1] = -r1; q2[2] = -r2;
            } else {
                // slots 28..31: zero two diagonal entries each
                const int d0 = (s - 28) * 2;
#pragma unroll
                for (int dd = 0; dd < 2; dd++) {
                    float* qd = outk + (d0 + dd) * (APITCH + 3);  // a==b
                    qd[0] = 0.0f; qd[1] = 0.0f; qd[2] = 0.0f;
                }
            }
        }
    }
    __syncthreads();

    // ---- coalesced copy-out: 2304 float4 per CTA, thread t owns f = t + 384q ----
    float4* obase = (float4*)(out + (size_t)bn * (KK * 192));
#pragma unroll
    for (int q = 0; q < 6; q++) {
        const int f   = t + THREADS * q;     // 0..2303
        const int kk  = f / 48;              // 48 float4 per k row
        const int rem = f - kk * 48;
        const int aa  = rem / 6;             // 6 float4 per a-row
        const int rr  = rem - aa * 6;
        const float4 v = *(const float4*)&sOut[kk * KPITCH + aa * APITCH + rr * 4];
        obase[f] = v;
    }
}

extern "C" void kernel_launch(void* const* d_in, const int* in_sizes, int n_in,
                              void* d_out, int out_size) {
    const float* X = (const float*)d_in[0];
    const int*   E = (const int*)d_in[1];
    const int*   C = (const int*)d_in[2];
    float* out = (float*)d_out;

    edge_orient_kernel<<<BB * NN, THREADS>>>(X, E, C, out);
}

// round 3
// speedup vs baseline: 1.8824x; 1.8824x over previous
#include <cuda_runtime.h>
#include <cuda_bf16.h>

// Shapes (fixed): B=2, N=2048, K=48, A=4
// X: (B,N,4,3) f32; edge_idx: (B,N,48) i32; C: (B,N) i32
// out: (B,N,48,192) f32   [192 floats per (b,n,k) = 64 pairs * 3 comps]
//
// Mapping: CTA per (b,n). Thread t writes output float4 index f = t + 384q
// (q=0..5) -> perfectly coalesced STG.128, no output staging.
// Each float4 straddles <=2 (a,b) pairs; thread recomputes both.
// Inputs staged once in smem: sA[k][atom(0..7)][3] (i-atoms replicated per k),
// per-k combined mask, frame R.

#define BB 2
#define NN 2048
#define KK 48
#define EPS 0.1f
#define THREADS 384

__global__ __launch_bounds__(THREADS) void edge_orient_kernel(
    const float* __restrict__ X,
    const int*   __restrict__ E,
    const int*   __restrict__ C,
    float*       __restrict__ out)
{
    const int bn = blockIdx.x;
    const int b  = bn >> 11;          // / NN
    const int t  = threadIdx.x;

    __shared__ __align__(16) float sA[KK][24];  // 8 atoms x 3 floats per k
    __shared__ float sM[KK];                    // mask_i * mask_j[k]
    __shared__ float sR[9];

    const int* e_row = E + (size_t)bn * KK;

    // ---- staging: 288 threads fill sA (row k, float4 qq of 6) ----
    if (t < KK * 6) {
        const int k  = t / 6;
        const int qq = t - k * 6;
        const float4* src;
        if (qq < 3) {
            src = (const float4*)(X + (size_t)bn * 12) + qq;          // i-atoms
            ((float4*)&sA[k][0])[qq] = *src;
        } else {
            const int j = e_row[k];
            src = (const float4*)(X + ((size_t)(b * NN + j)) * 12) + (qq - 3);
            ((float4*)&sA[k][0])[qq] = *src;                          // j-atoms
        }
    }
    if (t >= 288 && t < 288 + KK) {
        const int k = t - 288;
        const int j = e_row[k];
        sM[k] = ((C[bn] > 0) && (C[b * NN + j] > 0)) ? 1.0f : 0.0f;
    }
    if (t == 336) {
        const float* xr = X + (size_t)bn * 12;
        float Nx = xr[0], Ny = xr[1], Nz = xr[2];
        float Ax = xr[3], Ay = xr[4], Az = xr[5];
        float Cx = xr[6], Cy = xr[7], Cz = xr[8];

        float ux = Nx - Ax, uy = Ny - Ay, uz = Nz - Az;
        float inv = rsqrtf(ux*ux + uy*uy + uz*uz + EPS);
        float n1x = ux*inv, n1y = uy*inv, n1z = uz*inv;

        float vx = Cx - Ax, vy = Cy - Ay, vz = Cz - Az;
        inv = rsqrtf(vx*vx + vy*vy + vz*vz + EPS);
        vx *= inv; vy *= inv; vz *= inv;

        float c2x = n1y*vz - n1z*vy;
        float c2y = n1z*vx - n1x*vz;
        float c2z = n1x*vy - n1y*vx;
        inv = rsqrtf(c2x*c2x + c2y*c2y + c2z*c2z + EPS);
        float n2x = c2x*inv, n2y = c2y*inv, n2z = c2z*inv;

        float c3x = n1y*n2z - n1z*n2y;
        float c3y = n1z*n2x - n1x*n2z;
        float c3z = n1x*n2y - n1y*n2x;
        inv = rsqrtf(c3x*c3x + c3y*c3y + c3z*c3z + EPS);

        sR[0] = n1x;     sR[1] = n1y;     sR[2] = n1z;
        sR[3] = n2x;     sR[4] = n2y;     sR[5] = n2z;
        sR[6] = c3x*inv; sR[7] = c3y*inv; sR[8] = c3z*inv;
    }
    __syncthreads();

    const float n1x = sR[0], n1y = sR[1], n1z = sR[2];
    const float n2x = sR[3], n2y = sR[4], n2z = sR[5];
    const float n3x = sR[6], n3y = sR[7], n3z = sR[8];

    float4* obase = (float4*)(out + (size_t)bn * (KK * 192));

#pragma unroll
    for (int q = 0; q < 6; q++) {
        const int f = t + THREADS * q;       // 0..2303
        const int k = f / 48;
        const int r = f - k * 48;            // float4 index within k-row
        const int fr = 4 * r;                // first float index (0..188)
        const int s0 = fr / 3;               // first pair index
        const int c0 = fr - s0 * 3;          // component offset 0..2
        const int s1 = s0 + 1;               // second pair (may be unused)

        const float* row = &sA[k][0];
        const float  mk  = sM[k];

        // pair s0: a = s0>>3, b = s0&7
        const int a0 = (s0 >> 3) * 3, b0 = (s0 & 7) * 3;
        const int a1 = (s1 >> 3) * 3, b1 = (s1 & 7) * 3;

        float v0x, v0y, v0z, v1x, v1y, v1z;
        {
            const float dx = row[b0 + 0] - row[a0 + 0];
            const float dy = row[b0 + 1] - row[a0 + 1];
            const float dz = row[b0 + 2] - row[a0 + 2];
            const float inv = rsqrtf(dx*dx + dy*dy + dz*dz + EPS) * mk;
            const float ux = dx * inv, uy = dy * inv, uz = dz * inv;
            v0x = ux*n1x + uy*n1y + uz*n1z;
            v0y = ux*n2x + uy*n2y + uz*n2z;
            v0z = ux*n3x + uy*n3y + uz*n3z;
        }
        {
            const float dx = row[b1 + 0] - row[a1 + 0];
            const float dy = row[b1 + 1] - row[a1 + 1];
            const float dz = row[b1 + 2] - row[a1 + 2];
            const float inv = rsqrtf(dx*dx + dy*dy + dz*dz + EPS) * mk;
            const float ux = dx * inv, uy = dy * inv, uz = dz * inv;
            v1x = ux*n1x + uy*n1y + uz*n1z;
            v1y = ux*n2x + uy*n2y + uz*n2z;
            v1z = ux*n3x + uy*n3y + uz*n3z;
        }

        // assemble the 4 consecutive floats starting at component c0 of pair s0
        float4 o;
        if (c0 == 0)      { o.x = v0x; o.y = v0y; o.z = v0z; o.w = v1x; }
        else if (c0 == 1) { o.x = v0y; o.y = v0z; o.z = v1x; o.w = v1y; }
        else              { o.x = v0z; o.y = v1x; o.z = v1y; o.w = v1z; }

        obase[f] = o;
    }
}

extern "C" void kernel_launch(void* const* d_in, const int* in_sizes, int n_in,
                              void* d_out, int out_size) {
    const float* X = (const float*)d_in[0];
    const int*   E = (const int*)d_in[1];
    const int*   C = (const int*)d_in[2];
    float* out = (float*)d_out;

    edge_orient_kernel<<<BB * NN, THREADS>>>(X, E, C, out);
}

// round 5
// speedup vs baseline: 2.0000x; 1.0625x over previous
#include <cuda_runtime.h>
#include <cuda_bf16.h>

// Shapes (fixed): B=2, N=2048, K=48, A=4
// X: (B,N,4,3) f32; edge_idx: (B,N,48) i32; C: (B,N) i32
// out: (B,N,48,192) f32
//
// R = Q * diag(s1,s2,s3): columns of R are mutually orthogonal (cross
// products) but NOT unit (eps=0.1 in the normalizer). Q orthonormal,
// s_y = ||n_y||. Then U_rot[y] = s_y * (Q^T d)[y] * rsqrt(||d||^2 + eps),
// and ||d|| is preserved by the Q^T rotation. Rotate atoms once with Q^T,
// per pair: diff + rsqrt + per-axis scale (mask folded in).
//
// Thread t writes output float4 f = t + 384q (q=0..5): coalesced STG.128.
// 384 = 8*48 -> r = f%48 invariant across q; only k moves (ptr increments).

#define BB 2
#define NN 2048
#define KK 48
#define EPS 0.1f
#define THREADS 384
#define ROWF 24
#define KSTRIDE (8 * ROWF)

__global__ __launch_bounds__(THREADS) void edge_orient_kernel(
    const float* __restrict__ X,
    const int*   __restrict__ E,
    const int*   __restrict__ C,
    float*       __restrict__ out)
{
    const int bn = blockIdx.x;
    const int b  = bn >> 11;          // / NN
    const int t  = threadIdx.x;

    __shared__ __align__(16) float sA[KK][ROWF];  // Q^T-rotated coords
    __shared__ float sM[KK];
    __shared__ float sR[9];                        // rows of Q^T (q1,q2,q3)
    __shared__ float sS[3];                        // column scales s1,s2,s3

    const int* e_row = E + (size_t)bn * KK;

    // ---- phase 1: raw coords, masks, frame ----
    if (t < KK * 6) {
        const int k  = t / 6;
        const int qq = t - k * 6;
        if (qq < 3) {
            ((float4*)&sA[k][0])[qq] = ((const float4*)(X + (size_t)bn * 12))[qq];
        } else {
            const int j = e_row[k];
            ((float4*)&sA[k][0])[qq] =
                ((const float4*)(X + ((size_t)(b * NN + j)) * 12))[qq - 3];
        }
    }
    if (t >= 288 && t < 288 + KK) {
        const int k = t - 288;
        const int j = e_row[k];
        sM[k] = ((C[bn] > 0) && (C[b * NN + j] > 0)) ? 1.0f : 0.0f;
    }
    if (t == 336) {
        const float* xr = X + (size_t)bn * 12;
        float Nx = xr[0], Ny = xr[1], Nz = xr[2];
        float Ax = xr[3], Ay = xr[4], Az = xr[5];
        float Cx = xr[6], Cy = xr[7], Cz = xr[8];

        // n1 = normed_eps(N - CA); split into unit q1 and scale s1
        float ux = Nx - Ax, uy = Ny - Ay, uz = Nz - Az;
        float nu2  = ux*ux + uy*uy + uz*uz;
        float invE = rsqrtf(nu2 + EPS);
        float n1x = ux*invE, n1y = uy*invE, n1z = uz*invE;
        float n1n2 = n1x*n1x + n1y*n1y + n1z*n1z;
        float inv0 = rsqrtf(n1n2);
        float q1x = n1x*inv0, q1y = n1y*inv0, q1z = n1z*inv0;
        float s1  = n1n2 * inv0;      // ||n1||

        // v = normed_eps(C - CA)
        float vx = Cx - Ax, vy = Cy - Ay, vz = Cz - Az;
        float invV = rsqrtf(vx*vx + vy*vy + vz*vz + EPS);
        vx *= invV; vy *= invV; vz *= invV;

        // n2 = normed_eps(cross(n1, v))
        float c2x = n1y*vz - n1z*vy;
        float c2y = n1z*vx - n1x*vz;
        float c2z = n1x*vy - n1y*vx;
        float nc2 = c2x*c2x + c2y*c2y + c2z*c2z;
        invE = rsqrtf(nc2 + EPS);
        float n2x = c2x*invE, n2y = c2y*invE, n2z = c2z*invE;
        float n2n2 = n2x*n2x + n2y*n2y + n2z*n2z;
        inv0 = rsqrtf(n2n2);
        float q2x = n2x*inv0, q2y = n2y*inv0, q2z = n2z*inv0;
        float s2  = n2n2 * inv0;

        // n3 = normed_eps(cross(n1, n2))
        float c3x = n1y*n2z - n1z*n2y;
        float c3y = n1z*n2x - n1x*n2z;
        float c3z = n1x*n2y - n1y*n2x;
        float nc3 = c3x*c3x + c3y*c3y + c3z*c3z;
        invE = rsqrtf(nc3 + EPS);
        float n3x = c3x*invE, n3y = c3y*invE, n3z = c3z*invE;
        float n3n2 = n3x*n3x + n3y*n3y + n3z*n3z;
        inv0 = rsqrtf(n3n2);

        sR[0] = q1x;      sR[1] = q1y;      sR[2] = q1z;
        sR[3] = q2x;      sR[4] = q2y;      sR[5] = q2z;
        sR[6] = n3x*inv0; sR[7] = n3y*inv0; sR[8] = n3z*inv0;
        sS[0] = s1; sS[1] = s2; sS[2] = n3n2 * inv0;
    }
    __syncthreads();

    const float q1x = sR[0], q1y = sR[1], q1z = sR[2];
    const float q2x = sR[3], q2y = sR[4], q2z = sR[5];
    const float q3x = sR[6], q3y = sR[7], q3z = sR[8];
    const float s1 = sS[0], s2 = sS[1], s3 = sS[2];

    // ---- phase 2: rotate all atoms with Q^T (norm-preserving) ----
    {
        const int k = t >> 3;
        const int a = (t & 7) * 3;
        float* p = &sA[k][a];
        const float x = p[0], y = p[1], z = p[2];
        const float rx = x*q1x + y*q1y + z*q1z;
        const float ry = x*q2x + y*q2y + z*q2z;
        const float rz = x*q3x + y*q3y + z*q3z;
        __syncthreads();
        p[0] = rx; p[1] = ry; p[2] = rz;
    }
    __syncthreads();

    // ---- phase 3: outputs ----
    const int k0 = t / 48;
    const int r  = t - k0 * 48;
    const int fr = 4 * r;
    const int s0 = fr / 3;
    const int c0 = fr - s0 * 3;
    const int sp1 = s0 + 1;

    const int a0 = (s0  >> 3) * 3, b0 = (s0  & 7) * 3;
    const int a1 = (sp1 >> 3) * 3, b1 = (sp1 & 7) * 3;

    const float* pa0 = &sA[k0][a0];
    const float* pb0 = &sA[k0][b0];
    const float* pa1 = &sA[k0][a1];
    const float* pb1 = &sA[k0][b1];
    const float* pm  = &sM[k0];

    float4* op = (float4*)(out + (size_t)bn * (KK * 192)) + t;

#pragma unroll
    for (int q = 0; q < 6; q++) {
        const float mk  = *pm;
        const float ms1 = mk * s1, ms2 = mk * s2, ms3 = mk * s3;

        float v0x, v0y, v0z, v1x, v1y, v1z;
        {
            const float dx = pb0[0] - pa0[0];
            const float dy = pb0[1] - pa0[1];
            const float dz = pb0[2] - pa0[2];
            const float inv = rsqrtf(dx*dx + dy*dy + dz*dz + EPS);
            v0x = dx * inv * ms1; v0y = dy * inv * ms2; v0z = dz * inv * ms3;
        }
        {
            const float dx = pb1[0] - pa1[0];
            const float dy = pb1[1] - pa1[1];
            const float dz = pb1[2] - pa1[2];
            const float inv = rsqrtf(dx*dx + dy*dy + dz*dz + EPS);
            v1x = dx * inv * ms1; v1y = dy * inv * ms2; v1z = dz * inv * ms3;
        }

        float4 o;
        if (c0 == 0)      { o.x = v0x; o.y = v0y; o.z = v0z; o.w = v1x; }
        else if (c0 == 1) { o.x = v0y; o.y = v0z; o.z = v1x; o.w = v1y; }
        else              { o.x = v0z; o.y = v1x; o.z = v1y; o.w = v1z; }
        *op = o;

        pa0 += KSTRIDE; pb0 += KSTRIDE; pa1 += KSTRIDE; pb1 += KSTRIDE;
        pm  += 8;
        op  += THREADS;
    }
}

extern "C" void kernel_launch(void* const* d_in, const int* in_sizes, int n_in,
                              void* d_out, int out_size) {
    const float* X = (const float*)d_in[0];
    const int*   E = (const int*)d_in[1];
    const int*   C = (const int*)d_in[2];
    float* out = (float*)d_out;

    edge_orient_kernel<<<BB * NN, THREADS>>>(X, E, C, out);
}